// round 13
// baseline (speedup 1.0000x reference)
#include <cuda_runtime.h>
#include <cuda_fp16.h>
#include <math.h>
#include <stdint.h>

// Problem constants
#define S_TOK 4096
#define DIM   1024
#define NEXP  8
#define HID   4096
#define NSCORES (NEXP * S_TOK)

// ---------------- device scratch ----------------
__device__ float g_scores[NSCORES];
__device__ float g_thresh;
__device__ int   g_cnt[NEXP];
__device__ int   g_rows[NEXP * S_TOK];
__device__ float g_w[NEXP * S_TOK];
__device__ int   g_pos[NSCORES];
__device__ __half g_xh[(size_t)S_TOK * DIM];                     // fp16 x
__device__ unsigned g_w1p[(size_t)NEXP * (DIM / 2) * HID];       // fp16 k-pair packed
__device__ unsigned g_w2p[(size_t)NEXP * (HID / 2) * DIM];
__device__ __half g_hidden[(size_t)NEXP * S_TOK * HID];          // fp16
__device__ float g_y[(size_t)NEXP * S_TOK * DIM];

__device__ __forceinline__ unsigned pack2(float lo, float hi) {
    __half2 h = __floats2half2_rn(lo, hi);
    return *reinterpret_cast<unsigned*>(&h);
}

// w [E][K][N] fp32 -> wp [E][K/2][N] uint32 (halves k=2kp,2kp+1)
__global__ void pack_w_kernel(const float* __restrict__ w, unsigned* __restrict__ wp,
                              int K, int N) {
    size_t idx = (size_t)blockIdx.x * blockDim.x + threadIdx.x;   // one per 4 cols
    int nq = (int)(idx % (N / 4)) * 4;
    int kp = (int)((idx / (N / 4)) % (K / 2));
    int e  = (int)(idx / ((size_t)(N / 4) * (K / 2)));
    const float* s0 = w + ((size_t)e * K + 2 * kp) * N + nq;
    float4 r0 = *(const float4*)s0;
    float4 r1 = *(const float4*)(s0 + N);
    uint4 o;
    o.x = pack2(r0.x, r1.x); o.y = pack2(r0.y, r1.y);
    o.z = pack2(r0.z, r1.z); o.w = pack2(r0.w, r1.w);
    *(uint4*)&wp[((size_t)e * (K / 2) + kp) * N + nq] = o;
}

// ---------------- router (exact fp32) + fused x->fp16 convert ----------------
__global__ void router_kernel(const float* __restrict__ x,
                              const float* __restrict__ gw,
                              const float* __restrict__ eb) {
    int s = blockIdx.x;
    int warp = threadIdx.x >> 5, lane = threadIdx.x & 31;
    const float* xs = x + (size_t)s * DIM;
    const float* g  = gw + (size_t)warp * DIM;
    float acc = 0.f;
    for (int i = lane; i < DIM; i += 32) acc += xs[i] * g[i];
    #pragma unroll
    for (int o = 16; o; o >>= 1) acc += __shfl_xor_sync(0xFFFFFFFFu, acc, o);
    __shared__ float l[NEXP];
    if (lane == 0) l[warp] = acc + eb[warp];
    // fused convert of this token's row to fp16 (natural k order)
    {
        int i4 = threadIdx.x * 4;
        float4 v = *(const float4*)(xs + i4);
        uint2 o;
        o.x = pack2(v.x, v.y);
        o.y = pack2(v.z, v.w);
        *(uint2*)&g_xh[(size_t)s * DIM + i4] = o;
    }
    __syncthreads();
    if (threadIdx.x < NEXP) {
        float m = l[0];
        #pragma unroll
        for (int e = 1; e < NEXP; e++) m = fmaxf(m, l[e]);
        float sum = 0.f;
        #pragma unroll
        for (int e = 0; e < NEXP; e++) sum += expf(l[e] - m);
        g_scores[threadIdx.x * S_TOK + s] = expf(l[threadIdx.x] - m) / sum;
    }
}

// ---------------- exact global top-k threshold (radix select) ----------------
__global__ void topk_kernel(const int* __restrict__ cap) {
    __shared__ int hist[256];
    __shared__ unsigned sh_prefix;
    __shared__ int sh_k;
    if (threadIdx.x < NEXP) g_cnt[threadIdx.x] = 0;
    int k = S_TOK * cap[0];
    if (k < 1) k = 1;
    if (k > NSCORES) k = NSCORES;
    unsigned prefix = 0, mask = 0;
    int kk = k;
    for (int shift = 24; shift >= 0; shift -= 8) {
        for (int i = threadIdx.x; i < 256; i += blockDim.x) hist[i] = 0;
        __syncthreads();
        for (int i = threadIdx.x; i < NSCORES; i += blockDim.x) {
            unsigned u = __float_as_uint(g_scores[i]);
            if ((u & mask) == prefix) atomicAdd(&hist[(u >> shift) & 255], 1);
        }
        __syncthreads();
        if (threadIdx.x == 0) {
            int rem = kk, b = 255;
            for (; b >= 0; --b) {
                if (rem <= hist[b]) break;
                rem -= hist[b];
            }
            if (b < 0) b = 0;
            sh_prefix = prefix | ((unsigned)b << shift);
            sh_k = rem;
        }
        __syncthreads();
        prefix = sh_prefix;
        kk = sh_k;
        mask |= (0xFFu << shift);
        __syncthreads();
    }
    if (threadIdx.x == 0) g_thresh = __uint_as_float(prefix);
}

__global__ void build_kernel() {
    int i = blockIdx.x * blockDim.x + threadIdx.x;
    if (i >= NSCORES) return;
    float sc = g_scores[i];
    int e = i >> 12;
    int p = -1;
    if (sc >= g_thresh) {
        int r = atomicAdd(&g_cnt[e], 1);
        g_rows[e * S_TOK + r] = i & (S_TOK - 1);
        g_w[e * S_TOK + r]    = sc;
        p = r;
    }
    g_pos[i] = p;
}

// -- fp16 mma GEMM: 256 thr, warp 64x32, cp.async 6-stage ring, 2 stages/sync --
#define BM 128
#define BN 128
#define BK 16
#define NTHR 256
#define RSTAGES 6
#define ASTRW 12                               // A row stride (b32 words)
#define BSTRW 136                              // B row stride (b32 words)
#define A_WORDS (BM * ASTRW)                   // 1536
#define B_WORDS (8 * BSTRW)                    // 1088
#define STAGE_WORDS (A_WORDS + B_WORDS)        // 2624
#define STAGE_BYTES (STAGE_WORDS * 4)          // 10496
#define TOKS_OFF (RSTAGES * STAGE_BYTES)       // 62976
#define SMEM_TOTAL (TOKS_OFF + BM * 4)         // 63488

#define CP16(dst_s, src_g) \
    asm volatile("cp.async.cg.shared.global [%0], [%1], 16;" :: "r"(dst_s), "l"(src_g) : "memory")
#define CP_COMMIT() asm volatile("cp.async.commit_group;" ::: "memory")
#define CP_WAIT2()  asm volatile("cp.async.wait_group 2;" ::: "memory")

__device__ __forceinline__ void mma_f16(float* c, const unsigned* a, const unsigned* b) {
    asm volatile("mma.sync.aligned.m16n8k16.row.col.f32.f16.f16.f32 "
        "{%0,%1,%2,%3}, {%4,%5,%6,%7}, {%8,%9}, {%0,%1,%2,%3};"
        : "+f"(c[0]), "+f"(c[1]), "+f"(c[2]), "+f"(c[3])
        : "r"(a[0]), "r"(a[1]), "r"(a[2]), "r"(a[3]), "r"(b[0]), "r"(b[1]));
}
__device__ __forceinline__ uint32_t smem_u32(const void* p) {
    uint32_t a;
    asm("{ .reg .u64 t; cvta.to.shared.u64 t, %1; cvt.u32.u64 %0, t; }" : "=r"(a) : "l"(p));
    return a;
}

// warp tile 64x32: 4 m-tiles x 4 n-tiles of m16n8k16
__device__ __forceinline__ void compute_stage(const unsigned* stg,
                                              int wm, int wn, int gid, int tig,
                                              float acc[4][4][4]) {
    const unsigned* As = stg;
    const unsigned* Bs = stg + A_WORDS;
    unsigned af[4][4], bf[4][2];
    #pragma unroll
    for (int mt = 0; mt < 4; mt++) {
        int r = wm + mt * 16 + gid;
        af[mt][0] = As[r * ASTRW + tig];
        af[mt][1] = As[(r + 8) * ASTRW + tig];
        af[mt][2] = As[r * ASTRW + tig + 4];
        af[mt][3] = As[(r + 8) * ASTRW + tig + 4];
    }
    #pragma unroll
    for (int nt = 0; nt < 4; nt++) {
        int n = wn + nt * 8 + gid;
        bf[nt][0] = Bs[tig * BSTRW + n];
        bf[nt][1] = Bs[(tig + 4) * BSTRW + n];
    }
    #pragma unroll
    for (int mt = 0; mt < 4; mt++)
        #pragma unroll
        for (int nt = 0; nt < 4; nt++)
            mma_f16(acc[mt][nt], af[mt], bf[nt]);
}

// staging (256 thr, 2 cp each): A row=t&127 half=t>>7; B kp=t>>5 nq=(t&31)*4
#define STAGE_CP(slot, k0, aSrcH, bSrcW, ldbW, aDstB, bDstB, sbase)                     \
    do {                                                                                \
        uint32_t so_ = (sbase) + (uint32_t)(slot) * STAGE_BYTES;                        \
        CP16(so_ + (aDstB), (aSrcH) + (k0));                                            \
        CP16(so_ + (bDstB), (bSrcW) + (size_t)((k0) >> 1) * (ldbW));                    \
    } while (0)

// GEMM1: g_hidden[e][r][h] = gelu( xh[tok[r]] @ w1p[e] + b1[e] ),  K=DIM
__global__ __launch_bounds__(NTHR, 2)
void gemm1_kernel(const float* __restrict__ b1) {
    int e = blockIdx.z;
    int n = g_cnt[e];
    int row0 = blockIdx.y * BM;
    if (row0 >= n) return;
    int col0 = blockIdx.x * BN;
    const unsigned* Bg = g_w1p + (size_t)e * (DIM / 2) * HID;
    const int ldbW = HID;
    const int KITS = DIM / BK;        // 64 stages
    const int KIT2 = KITS / 2;        // 32 barriers

    extern __shared__ char smem[];
    int* toks = (int*)(smem + TOKS_OFF);
    int tid = threadIdx.x;
    if (tid < BM) {
        int mg = row0 + tid;
        if (mg >= n) mg = n - 1;
        toks[tid] = g_rows[e * S_TOK + mg];
    }
    __syncthreads();

    int lane = tid & 31, warp = tid >> 5;
    int gid = lane >> 2, tig = lane & 3;
    int wm = (warp & 1) * 64, wn = (warp >> 1) * 32;

    int aR = tid & 127, aH = (tid >> 7) * 8;
    const __half* aSrcH = g_xh + (size_t)toks[aR] * DIM + aH;
    int kp = tid >> 5, nq = (tid & 31) * 4;
    const unsigned* bSrcW = Bg + (size_t)kp * ldbW + col0 + nq;
    uint32_t aDstB = (uint32_t)((aR * ASTRW + (aH >> 1)) * 4);
    uint32_t bDstB = (uint32_t)((A_WORDS + kp * BSTRW + nq) * 4);
    uint32_t sbase = smem_u32(smem);

    float acc[4][4][4];
    #pragma unroll
    for (int mt = 0; mt < 4; mt++)
        #pragma unroll
        for (int nt = 0; nt < 4; nt++)
            #pragma unroll
            for (int i = 0; i < 4; i++) acc[mt][nt][i] = 0.f;

    #pragma unroll
    for (int s = 0; s < 4; s++) {
        STAGE_CP(s, s * BK, aSrcH, bSrcW, ldbW, aDstB, bDstB, sbase);
        CP_COMMIT();
    }

    for (int it = 0; it < KIT2; it++) {
        CP_WAIT2();
        __syncthreads();
        int s0i = 2 * it + 4, s1i = 2 * it + 5;
        if (s0i < KITS) STAGE_CP(s0i % RSTAGES, s0i * BK, aSrcH, bSrcW, ldbW, aDstB, bDstB, sbase);
        CP_COMMIT();
        if (s1i < KITS) STAGE_CP(s1i % RSTAGES, s1i * BK, aSrcH, bSrcW, ldbW, aDstB, bDstB, sbase);
        CP_COMMIT();
        compute_stage((const unsigned*)(smem + (size_t)((2 * it) % RSTAGES) * STAGE_BYTES),
                      wm, wn, gid, tig, acc);
        compute_stage((const unsigned*)(smem + (size_t)((2 * it + 1) % RSTAGES) * STAGE_BYTES),
                      wm, wn, gid, tig, acc);
    }

    const float* b1e = b1 + (size_t)e * HID;
    __half* Hb = g_hidden + (size_t)e * S_TOK * HID;
    #pragma unroll
    for (int mt = 0; mt < 4; mt++) {
        #pragma unroll
        for (int half = 0; half < 2; half++) {
            int r = row0 + wm + mt * 16 + gid + half * 8;
            if (r >= n) continue;
            #pragma unroll
            for (int nt = 0; nt < 4; nt++) {
                int c = col0 + wn + nt * 8 + 2 * tig;
                float v0 = acc[mt][nt][half * 2 + 0] + b1e[c];
                float v1 = acc[mt][nt][half * 2 + 1] + b1e[c + 1];
                float t0 = tanhf(0.7978845608028654f * (v0 + 0.044715f * v0 * v0 * v0));
                float t1 = tanhf(0.7978845608028654f * (v1 + 0.044715f * v1 * v1 * v1));
                float g0 = 0.5f * v0 * (1.0f + t0);
                float g1 = 0.5f * v1 * (1.0f + t1);
                *(unsigned*)&Hb[(size_t)r * HID + c] = pack2(g0, g1);
            }
        }
    }
}

// GEMM2: g_y[e][r][d] = g_w[r] * ( g_hidden[e][r] @ w2p[e] + b2[e] ),  K=HID
__global__ __launch_bounds__(NTHR, 2)
void gemm2_kernel(const float* __restrict__ b2) {
    int e = blockIdx.z;
    int n = g_cnt[e];
    int row0 = blockIdx.y * BM;
    if (row0 >= n) return;
    int col0 = blockIdx.x * BN;
    const unsigned* Bg = g_w2p + (size_t)e * (HID / 2) * DIM;
    const int ldbW = DIM;
    const int KITS = HID / BK;        // 256 stages
    const int KIT2 = KITS / 2;        // 128 barriers

    extern __shared__ char smem[];
    int tid = threadIdx.x;
    int lane = tid & 31, warp = tid >> 5;
    int gid = lane >> 2, tig = lane & 3;
    int wm = (warp & 1) * 64, wn = (warp >> 1) * 32;

    int aR = tid & 127, aH = (tid >> 7) * 8;
    int mg = row0 + aR; if (mg >= n) mg = n - 1;
    const __half* aSrcH = g_hidden + ((size_t)e * S_TOK + mg) * HID + aH;
    int kp = tid >> 5, nq = (tid & 31) * 4;
    const unsigned* bSrcW = Bg + (size_t)kp * ldbW + col0 + nq;
    uint32_t aDstB = (uint32_t)((aR * ASTRW + (aH >> 1)) * 4);
    uint32_t bDstB = (uint32_t)((A_WORDS + kp * BSTRW + nq) * 4);
    uint32_t sbase = smem_u32(smem);

    float acc[4][4][4];
    #pragma unroll
    for (int mt = 0; mt < 4; mt++)
        #pragma unroll
        for (int nt = 0; nt < 4; nt++)
            #pragma unroll
            for (int i = 0; i < 4; i++) acc[mt][nt][i] = 0.f;

    #pragma unroll
    for (int s = 0; s < 4; s++) {
        STAGE_CP(s, s * BK, aSrcH, bSrcW, ldbW, aDstB, bDstB, sbase);
        CP_COMMIT();
    }

    for (int it = 0; it < KIT2; it++) {
        CP_WAIT2();
        __syncthreads();
        int s0i = 2 * it + 4, s1i = 2 * it + 5;
        if (s0i < KITS) STAGE_CP(s0i % RSTAGES, s0i * BK, aSrcH, bSrcW, ldbW, aDstB, bDstB, sbase);
        CP_COMMIT();
        if (s1i < KITS) STAGE_CP(s1i % RSTAGES, s1i * BK, aSrcH, bSrcW, ldbW, aDstB, bDstB, sbase);
        CP_COMMIT();
        compute_stage((const unsigned*)(smem + (size_t)((2 * it) % RSTAGES) * STAGE_BYTES),
                      wm, wn, gid, tig, acc);
        compute_stage((const unsigned*)(smem + (size_t)((2 * it + 1) % RSTAGES) * STAGE_BYTES),
                      wm, wn, gid, tig, acc);
    }

    const float* b2e = b2 + (size_t)e * DIM;
    #pragma unroll
    for (int mt = 0; mt < 4; mt++) {
        #pragma unroll
        for (int half = 0; half < 2; half++) {
            int r = row0 + wm + mt * 16 + gid + half * 8;
            if (r >= n) continue;
            float wg = g_w[e * S_TOK + r];
            #pragma unroll
            for (int nt = 0; nt < 4; nt++) {
                int c = col0 + wn + nt * 8 + 2 * tig;
                float2 o;
                o.x = wg * (acc[mt][nt][half * 2 + 0] + b2e[c]);
                o.y = wg * (acc[mt][nt][half * 2 + 1] + b2e[c + 1]);
                *(float2*)&g_y[((size_t)e * S_TOK + r) * DIM + c] = o;
            }
        }
    }
}

// ---------------- deterministic combine (1 block/token, float4) -------------
__global__ void combine_kernel(float* __restrict__ out) {
    int s = blockIdx.x;
    __shared__ int pos[NEXP];
    if (threadIdx.x < NEXP) pos[threadIdx.x] = g_pos[threadIdx.x * S_TOK + s];
    __syncthreads();
    int d = threadIdx.x * 4;
    float4 acc = make_float4(0.f, 0.f, 0.f, 0.f);
    #pragma unroll
    for (int e = 0; e < NEXP; e++) {
        int p = pos[e];
        if (p >= 0) {
            float4 v = *(const float4*)&g_y[((size_t)(e * S_TOK + p)) * DIM + d];
            acc.x += v.x; acc.y += v.y; acc.z += v.z; acc.w += v.w;
        }
    }
    *(float4*)&out[(size_t)s * DIM + d] = acc;
}

// ---------------- launch ----------------
extern "C" void kernel_launch(void* const* d_in, const int* in_sizes, int n_in,
                              void* d_out, int out_size) {
    const float* x  = (const float*)d_in[0];
    const float* gw = (const float*)d_in[1];
    const float* eb = (const float*)d_in[2];
    const float* w1 = (const float*)d_in[3];
    const float* b1 = (const float*)d_in[4];
    const float* w2 = (const float*)d_in[5];
    const float* b2 = (const float*)d_in[6];
    const int*  cap = (const int*)d_in[7];
    float* out = (float*)d_out;

    cudaFuncSetAttribute(gemm1_kernel, cudaFuncAttributeMaxDynamicSharedMemorySize, SMEM_TOTAL);
    cudaFuncSetAttribute(gemm2_kernel, cudaFuncAttributeMaxDynamicSharedMemorySize, SMEM_TOTAL);

    unsigned *w1p, *w2p;
    cudaGetSymbolAddress((void**)&w1p, g_w1p);
    cudaGetSymbolAddress((void**)&w2p, g_w2p);

    pack_w_kernel<<<(NEXP * (DIM / 2) * (HID / 4)) / 256, 256>>>(w1, w1p, DIM, HID);
    pack_w_kernel<<<(NEXP * (HID / 2) * (DIM / 4)) / 256, 256>>>(w2, w2p, HID, DIM);

    router_kernel<<<S_TOK, 256>>>(x, gw, eb);
    topk_kernel<<<1, 256>>>(cap);
    build_kernel<<<NSCORES / 256, 256>>>();
    gemm1_kernel<<<dim3(HID / BN, S_TOK / BM, NEXP), NTHR, SMEM_TOTAL>>>(b1);
    gemm2_kernel<<<dim3(DIM / BN, S_TOK / BM, NEXP), NTHR, SMEM_TOTAL>>>(b2);
    combine_kernel<<<S_TOK, 256>>>(out);
}

// round 14
// speedup vs baseline: 1.0533x; 1.0533x over previous
#include <cuda_runtime.h>
#include <cuda_fp16.h>
#include <math.h>
#include <stdint.h>

// Problem constants
#define S_TOK 4096
#define DIM   1024
#define NEXP  8
#define HID   4096
#define NSCORES (NEXP * S_TOK)

// ---------------- device scratch ----------------
__device__ float g_scores[NSCORES];
__device__ float g_thresh;
__device__ int   g_cnt[NEXP];
__device__ int   g_rows[NEXP * S_TOK];
__device__ float g_w[NEXP * S_TOK];
__device__ int   g_pos[NSCORES];
__device__ __half g_hidden[(size_t)NEXP * S_TOK * HID];   // fp16, k-pair packed
__device__ float g_y[(size_t)NEXP * S_TOK * DIM];
// parallel top-k state
__device__ int      g_hist4[4][256];
__device__ unsigned g_prefix;
__device__ int      g_kk;

// ---------------- router (exact fp32, x staged via smem) ----------------
__global__ void router_kernel(const float* __restrict__ x,
                              const float* __restrict__ gw,
                              const float* __restrict__ eb) {
    int s = blockIdx.x;
    int warp = threadIdx.x >> 5, lane = threadIdx.x & 31;
    __shared__ float xsh[DIM];
    {
        int i4 = threadIdx.x * 4;
        *(float4*)&xsh[i4] = *(const float4*)(x + (size_t)s * DIM + i4);
    }
    __syncthreads();
    const float* g = gw + (size_t)warp * DIM;
    float acc = 0.f;
    for (int i = lane; i < DIM; i += 32) acc += xsh[i] * g[i];
    #pragma unroll
    for (int o = 16; o; o >>= 1) acc += __shfl_xor_sync(0xFFFFFFFFu, acc, o);
    __shared__ float l[NEXP];
    if (lane == 0) l[warp] = acc + eb[warp];
    __syncthreads();
    if (threadIdx.x < NEXP) {
        float m = l[0];
        #pragma unroll
        for (int e = 1; e < NEXP; e++) m = fmaxf(m, l[e]);
        float sum = 0.f;
        #pragma unroll
        for (int e = 0; e < NEXP; e++) sum += expf(l[e] - m);
        g_scores[threadIdx.x * S_TOK + s] = expf(l[threadIdx.x] - m) / sum;
    }
}

// ---------------- parallel exact top-k threshold (radix select) ----------------
__global__ void topk_init_kernel(const int* __restrict__ cap) {
    int t = blockIdx.x * blockDim.x + threadIdx.x;
    if (t < 1024) ((int*)g_hist4)[t] = 0;
    if (t < NEXP) g_cnt[t] = 0;
    if (t == 0) {
        int k = S_TOK * cap[0];
        if (k < 1) k = 1;
        if (k > NSCORES) k = NSCORES;
        g_kk = k;
        g_prefix = 0u;
    }
}

__global__ void topk_scan_kernel(int pass) {
    int shift = 24 - pass * 8;
    unsigned mask = (pass == 0) ? 0u : (0xFFFFFFFFu << (32 - 8 * pass));
    unsigned prefix = g_prefix;
    __shared__ int hist[256];
    for (int i = threadIdx.x; i < 256; i += blockDim.x) hist[i] = 0;
    __syncthreads();
    for (int i = blockIdx.x * blockDim.x + threadIdx.x; i < NSCORES;
         i += gridDim.x * blockDim.x) {
        unsigned u = __float_as_uint(g_scores[i]);
        if ((u & mask) == prefix) atomicAdd(&hist[(u >> shift) & 255], 1);
    }
    __syncthreads();
    for (int i = threadIdx.x; i < 256; i += blockDim.x)
        if (hist[i]) atomicAdd(&g_hist4[pass][i], hist[i]);
}

__global__ void topk_reduce_kernel(int pass) {
    if (threadIdx.x == 0) {
        int shift = 24 - pass * 8;
        int rem = g_kk;
        int b = 255;
        for (; b >= 0; --b) {
            int h = g_hist4[pass][b];
            if (rem <= h) break;
            rem -= h;
        }
        if (b < 0) b = 0;
        g_prefix |= ((unsigned)b << shift);
        g_kk = rem;
        if (pass == 3) g_thresh = __uint_as_float(g_prefix);
    }
}

__global__ void build_kernel() {
    int i = blockIdx.x * blockDim.x + threadIdx.x;
    if (i >= NSCORES) return;
    float sc = g_scores[i];
    int e = i >> 12;
    int p = -1;
    if (sc >= g_thresh) {
        int r = atomicAdd(&g_cnt[e], 1);
        g_rows[e * S_TOK + r] = i & (S_TOK - 1);
        g_w[e * S_TOK + r]    = sc;
        p = r;
    }
    g_pos[i] = p;
}

// ---------------- fp16 tensor-core GEMM (m16n8k16, smem double-buffered) ----
// (exact R10 configuration — empirically fastest)
#define BM 128
#define BN 128
#define BK 16
#define ASTRW 12      // As row stride in b32 words (8 data + 4 pad)
#define BSTRW 136     // Bs row stride in b32 words
#define A_WORDS (BM * ASTRW)
#define B_WORDS (8 * BSTRW)

__device__ __forceinline__ void mma_f16(float* c, const unsigned* a, const unsigned* b) {
    asm volatile("mma.sync.aligned.m16n8k16.row.col.f32.f16.f16.f32 "
        "{%0,%1,%2,%3}, {%4,%5,%6,%7}, {%8,%9}, {%0,%1,%2,%3};"
        : "+f"(c[0]), "+f"(c[1]), "+f"(c[2]), "+f"(c[3])
        : "r"(a[0]), "r"(a[1]), "r"(a[2]), "r"(a[3]), "r"(b[0]), "r"(b[1]));
}
__device__ __forceinline__ unsigned pack2(float lo, float hi) {
    __half2 h = __floats2half2_rn(lo, hi);
    return *reinterpret_cast<unsigned*>(&h);
}

__device__ __forceinline__ void compute_bk16(const unsigned* As, const unsigned* Bs,
                                             int wm, int wn, int gid, int tig,
                                             float acc[4][4][4]) {
    unsigned af[4][4], bf[4][2];
    #pragma unroll
    for (int mt = 0; mt < 4; mt++) {
        int r = wm + mt * 16 + gid;
        af[mt][0] = As[r * ASTRW + tig];
        af[mt][1] = As[(r + 8) * ASTRW + tig];
        af[mt][2] = As[r * ASTRW + tig + 4];
        af[mt][3] = As[(r + 8) * ASTRW + tig + 4];
    }
    #pragma unroll
    for (int nt = 0; nt < 4; nt++) {
        int n = wn + nt * 8 + gid;
        bf[nt][0] = Bs[tig * BSTRW + n];
        bf[nt][1] = Bs[(tig + 4) * BSTRW + n];
    }
    #pragma unroll
    for (int mt = 0; mt < 4; mt++)
        #pragma unroll
        for (int nt = 0; nt < 4; nt++)
            mma_f16(acc[mt][nt], af[mt], bf[nt]);
}

// GEMM1: g_hidden[e][r][h] = gelu( x[tok[r]] @ w1[e] + b1[e] ),  K=DIM
__global__ __launch_bounds__(256, 2)
void gemm1_kernel(const float* __restrict__ x,
                  const float* __restrict__ w1,
                  const float* __restrict__ b1) {
    int e = blockIdx.z;
    int n = g_cnt[e];
    int row0 = blockIdx.y * BM;
    if (row0 >= n) return;
    int col0 = blockIdx.x * BN;
    const float* Bg = w1 + (size_t)e * DIM * HID;
    const int ldb = HID;
    const int KIT = DIM / BK;

    __shared__ __align__(16) unsigned As[2][A_WORDS];
    __shared__ __align__(16) unsigned Bs[2][B_WORDS];
    __shared__ int toks[BM];

    int tid = threadIdx.x;
    if (tid < BM) {
        int mg = row0 + tid;
        if (mg >= n) mg = n - 1;
        toks[tid] = g_rows[e * S_TOK + mg];
    }
    __syncthreads();

    int lane = tid & 31, warp = tid >> 5;
    int gid = lane >> 2, tig = lane & 3;
    int wm = (warp & 1) * 64, wn = (warp >> 1) * 32;

    float acc[4][4][4];
    #pragma unroll
    for (int mt = 0; mt < 4; mt++)
        #pragma unroll
        for (int nt = 0; nt < 4; nt++)
            #pragma unroll
            for (int i = 0; i < 4; i++) acc[mt][nt][i] = 0.f;

    int aR = tid >> 1, grp = tid & 1;
    const float* aSrc = x + (size_t)toks[aR] * DIM + grp * 8;
    int kp = warp, bn0 = lane * 4;
    const float* bSrcE = Bg + (size_t)(2 * kp) * ldb + col0 + bn0;
    const float* bSrcO = bSrcE + ldb;
    unsigned aOff = aR * ASTRW + grp * 4;
    unsigned bOff = kp * BSTRW + bn0;

    float ra[8];
    float4 rbE, rbO;
    *(float4*)&ra[0] = *(const float4*)aSrc;
    *(float4*)&ra[4] = *(const float4*)(aSrc + 4);
    rbE = *(const float4*)bSrcE;
    rbO = *(const float4*)bSrcO;
    {
        uint4 aw;
        aw.x = pack2(ra[0], ra[1]); aw.y = pack2(ra[2], ra[3]);
        aw.z = pack2(ra[4], ra[5]); aw.w = pack2(ra[6], ra[7]);
        *(uint4*)&As[0][aOff] = aw;
        uint4 bw;
        bw.x = pack2(rbE.x, rbO.x); bw.y = pack2(rbE.y, rbO.y);
        bw.z = pack2(rbE.z, rbO.z); bw.w = pack2(rbE.w, rbO.w);
        *(uint4*)&Bs[0][bOff] = bw;
    }
    __syncthreads();
    *(float4*)&ra[0] = *(const float4*)(aSrc + BK);
    *(float4*)&ra[4] = *(const float4*)(aSrc + BK + 4);
    rbE = *(const float4*)(bSrcE + (size_t)BK * ldb);
    rbO = *(const float4*)(bSrcO + (size_t)BK * ldb);

    for (int it = 0; it < KIT; it++) {
        int cur = it & 1;
        if (it + 1 < KIT) {
            uint4 aw;
            aw.x = pack2(ra[0], ra[1]); aw.y = pack2(ra[2], ra[3]);
            aw.z = pack2(ra[4], ra[5]); aw.w = pack2(ra[6], ra[7]);
            *(uint4*)&As[cur ^ 1][aOff] = aw;
            uint4 bw;
            bw.x = pack2(rbE.x, rbO.x); bw.y = pack2(rbE.y, rbO.y);
            bw.z = pack2(rbE.z, rbO.z); bw.w = pack2(rbE.w, rbO.w);
            *(uint4*)&Bs[cur ^ 1][bOff] = bw;
        }
        if (it + 2 < KIT) {
            int k0 = (it + 2) * BK;
            *(float4*)&ra[0] = *(const float4*)(aSrc + k0);
            *(float4*)&ra[4] = *(const float4*)(aSrc + k0 + 4);
            rbE = *(const float4*)(bSrcE + (size_t)k0 * ldb);
            rbO = *(const float4*)(bSrcO + (size_t)k0 * ldb);
        }
        compute_bk16(As[cur], Bs[cur], wm, wn, gid, tig, acc);
        __syncthreads();
    }

    const float* b1e = b1 + (size_t)e * HID;
    __half* Hb = g_hidden + (size_t)e * S_TOK * HID;
    #pragma unroll
    for (int mt = 0; mt < 4; mt++) {
        #pragma unroll
        for (int half = 0; half < 2; half++) {
            int r = row0 + wm + mt * 16 + gid + half * 8;
            if (r >= n) continue;
            #pragma unroll
            for (int nt = 0; nt < 4; nt++) {
                int c = col0 + wn + nt * 8 + 2 * tig;
                float v0 = acc[mt][nt][half * 2 + 0] + b1e[c];
                float v1 = acc[mt][nt][half * 2 + 1] + b1e[c + 1];
                float t0 = tanhf(0.7978845608028654f * (v0 + 0.044715f * v0 * v0 * v0));
                float t1 = tanhf(0.7978845608028654f * (v1 + 0.044715f * v1 * v1 * v1));
                float g0 = 0.5f * v0 * (1.0f + t0);
                float g1 = 0.5f * v1 * (1.0f + t1);
                *(unsigned*)&Hb[(size_t)r * HID + c] = pack2(g0, g1);
            }
        }
    }
}

// GEMM2: g_y[e][r][d] = g_w[r] * ( g_hidden[e][r] @ w2[e] + b2[e] ),  K=HID
__global__ __launch_bounds__(256, 2)
void gemm2_kernel(const float* __restrict__ w2,
                  const float* __restrict__ b2) {
    int e = blockIdx.z;
    int n = g_cnt[e];
    int row0 = blockIdx.y * BM;
    if (row0 >= n) return;
    int col0 = blockIdx.x * BN;
    const __half* Ag = g_hidden + (size_t)e * S_TOK * HID;
    const float* Bg = w2 + (size_t)e * HID * DIM;
    const int ldb = DIM;
    const int KIT = HID / BK;

    __shared__ __align__(16) unsigned As[2][A_WORDS];
    __shared__ __align__(16) unsigned Bs[2][B_WORDS];

    int tid = threadIdx.x;
    int lane = tid & 31, warp = tid >> 5;
    int gid = lane >> 2, tig = lane & 3;
    int wm = (warp & 1) * 64, wn = (warp >> 1) * 32;

    float acc[4][4][4];
    #pragma unroll
    for (int mt = 0; mt < 4; mt++)
        #pragma unroll
        for (int nt = 0; nt < 4; nt++)
            #pragma unroll
            for (int i = 0; i < 4; i++) acc[mt][nt][i] = 0.f;

    int aR = tid >> 1, grp = tid & 1;
    int mg = row0 + aR; if (mg >= n) mg = n - 1;
    const __half* aSrc = Ag + (size_t)mg * HID + grp * 8;   // fp16 k-pairs
    int kp = warp, bn0 = lane * 4;
    const float* bSrcE = Bg + (size_t)(2 * kp) * ldb + col0 + bn0;
    const float* bSrcO = bSrcE + ldb;
    unsigned aOff = aR * ASTRW + grp * 4;
    unsigned bOff = kp * BSTRW + bn0;

    uint4 ra;
    float4 rbE, rbO;
    ra = *(const uint4*)aSrc;
    rbE = *(const float4*)bSrcE;
    rbO = *(const float4*)bSrcO;
    {
        *(uint4*)&As[0][aOff] = ra;
        uint4 bw;
        bw.x = pack2(rbE.x, rbO.x); bw.y = pack2(rbE.y, rbO.y);
        bw.z = pack2(rbE.z, rbO.z); bw.w = pack2(rbE.w, rbO.w);
        *(uint4*)&Bs[0][bOff] = bw;
    }
    __syncthreads();
    ra = *(const uint4*)(aSrc + BK);
    rbE = *(const float4*)(bSrcE + (size_t)BK * ldb);
    rbO = *(const float4*)(bSrcO + (size_t)BK * ldb);

    for (int it = 0; it < KIT; it++) {
        int cur = it & 1;
        if (it + 1 < KIT) {
            *(uint4*)&As[cur ^ 1][aOff] = ra;
            uint4 bw;
            bw.x = pack2(rbE.x, rbO.x); bw.y = pack2(rbE.y, rbO.y);
            bw.z = pack2(rbE.z, rbO.z); bw.w = pack2(rbE.w, rbO.w);
            *(uint4*)&Bs[cur ^ 1][bOff] = bw;
        }
        if (it + 2 < KIT) {
            int k0 = (it + 2) * BK;
            ra = *(const uint4*)(aSrc + k0);
            rbE = *(const float4*)(bSrcE + (size_t)k0 * ldb);
            rbO = *(const float4*)(bSrcO + (size_t)k0 * ldb);
        }
        compute_bk16(As[cur], Bs[cur], wm, wn, gid, tig, acc);
        __syncthreads();
    }

    const float* b2e = b2 + (size_t)e * DIM;
    #pragma unroll
    for (int mt = 0; mt < 4; mt++) {
        #pragma unroll
        for (int half = 0; half < 2; half++) {
            int r = row0 + wm + mt * 16 + gid + half * 8;
            if (r >= n) continue;
            float wg = g_w[e * S_TOK + r];
            #pragma unroll
            for (int nt = 0; nt < 4; nt++) {
                int c = col0 + wn + nt * 8 + 2 * tig;
                float2 o;
                o.x = wg * (acc[mt][nt][half * 2 + 0] + b2e[c]);
                o.y = wg * (acc[mt][nt][half * 2 + 1] + b2e[c + 1]);
                *(float2*)&g_y[((size_t)e * S_TOK + r) * DIM + c] = o;
            }
        }
    }
}

// ---------------- deterministic combine (1 block/token, float4) -------------
__global__ void combine_kernel(float* __restrict__ out) {
    int s = blockIdx.x;
    __shared__ int pos[NEXP];
    if (threadIdx.x < NEXP) pos[threadIdx.x] = g_pos[threadIdx.x * S_TOK + s];
    __syncthreads();
    int d = threadIdx.x * 4;
    float4 acc = make_float4(0.f, 0.f, 0.f, 0.f);
    #pragma unroll
    for (int e = 0; e < NEXP; e++) {
        int p = pos[e];
        if (p >= 0) {
            float4 v = *(const float4*)&g_y[((size_t)(e * S_TOK + p)) * DIM + d];
            acc.x += v.x; acc.y += v.y; acc.z += v.z; acc.w += v.w;
        }
    }
    *(float4*)&out[(size_t)s * DIM + d] = acc;
}

// ---------------- launch ----------------
extern "C" void kernel_launch(void* const* d_in, const int* in_sizes, int n_in,
                              void* d_out, int out_size) {
    const float* x  = (const float*)d_in[0];
    const float* gw = (const float*)d_in[1];
    const float* eb = (const float*)d_in[2];
    const float* w1 = (const float*)d_in[3];
    const float* b1 = (const float*)d_in[4];
    const float* w2 = (const float*)d_in[5];
    const float* b2 = (const float*)d_in[6];
    const int*  cap = (const int*)d_in[7];
    float* out = (float*)d_out;

    router_kernel<<<S_TOK, 256>>>(x, gw, eb);
    topk_init_kernel<<<4, 256>>>(cap);
    for (int pass = 0; pass < 4; pass++) {
        topk_scan_kernel<<<64, 256>>>(pass);
        topk_reduce_kernel<<<1, 32>>>(pass);
    }
    build_kernel<<<NSCORES / 256, 256>>>();
    gemm1_kernel<<<dim3(HID / BN, S_TOK / BM, NEXP), 256>>>(x, w1, b1);
    gemm2_kernel<<<dim3(DIM / BN, S_TOK / BM, NEXP), 256>>>(w2, b2);
    combine_kernel<<<S_TOK, 256>>>(out);
}